// round 8
// baseline (speedup 1.0000x reference)
#include <cuda_runtime.h>
#include <math.h>

#define NN 50000
#define EE 800000
#define HH 64
#define FF 64
#define CC 10
#define KK 4
#define LL 3
#define NB_BATCH 256
#define SPAD 68
#define WSPS 132   // floats per kk2 row in packed weight smem (64 float2 + pad)

// ---------------- device scratch ----------------
__device__ float g_Z[NN * HH];
__device__ float g_h0[(size_t)NN * KK * HH];   // interleaved [n][k][64]
__device__ float g_h1[(size_t)NN * KK * HH];   // interleaved [n][k][64]
__device__ float g_AB[(size_t)KK * NN * 128];
__device__ float g_ewc[(size_t)EE * KK];       // CSR-edge-major weights [p][k]
__device__ int   g_deg[NN];
__device__ int   g_off[NN + 1];
__device__ int   g_fill[NN];
__device__ int   g_csr_src[EE];
__device__ int   g_csr_dst[EE];
__device__ int   g_csr_eid[EE];
__device__ float g_poolZ[NB_BATCH * HH];
__device__ float g_poolS[KK * NB_BATCH * HH];
__device__ int   g_cnt[NB_BATCH];

__device__ __forceinline__ void red_add_f4(float4* p, float4 v) {
    asm volatile("red.global.add.v4.f32 [%0], {%1,%2,%3,%4};"
                 :: "l"(p), "f"(v.x), "f"(v.y), "f"(v.z), "f"(v.w) : "memory");
}
__device__ __forceinline__ float sigmoidf_(float v) { return 1.0f / (1.0f + expf(-v)); }

// pack 64x64 row-major W[k][j] into Wsp[kk2][j] = (W[2kk2][j], W[2kk2+1][j])
__device__ __forceinline__ void loadWp(const float* __restrict__ W, float* Wsp, int tid) {
    #pragma unroll
    for (int it = 0; it < 8; it++) {
        int idx = it * 256 + tid;        // 0..2047
        int kk2 = idx >> 6;              // 0..31
        int j = idx & 63;
        float2 v;
        v.x = W[(2 * kk2) * 64 + j];
        v.y = W[(2 * kk2 + 1) * 64 + j];
        *((float2*)&Wsp[kk2 * WSPS + j * 2]) = v;
    }
}

// 64x64x64 GEMM, pairwise-K packed f32x2: As row-major [row][k], Wsp packed.
// acc[i][j] for rows ty*4+i, cols tx*4+j.
__device__ __forceinline__ void gemm64p(const float* As, const float* Wsp,
                                        float acc[4][4], int tx, int ty) {
    unsigned long long acc2[4][4];
    #pragma unroll
    for (int i = 0; i < 4; i++)
        #pragma unroll
        for (int j = 0; j < 4; j++) acc2[i][j] = 0ULL;
    #pragma unroll
    for (int kk2 = 0; kk2 < 32; kk2++) {
        ulonglong2 bA = *((const ulonglong2*)&Wsp[kk2 * WSPS + tx * 8]);
        ulonglong2 bB = *((const ulonglong2*)&Wsp[kk2 * WSPS + tx * 8 + 4]);
        unsigned long long b0 = bA.x, b1 = bA.y, b2 = bB.x, b3 = bB.y;
        #pragma unroll
        for (int i = 0; i < 4; i++) {
            unsigned long long a =
                *((const unsigned long long*)&As[(ty * 4 + i) * SPAD + kk2 * 2]);
            asm("fma.rn.f32x2 %0, %1, %2, %0;" : "+l"(acc2[i][0]) : "l"(a), "l"(b0));
            asm("fma.rn.f32x2 %0, %1, %2, %0;" : "+l"(acc2[i][1]) : "l"(a), "l"(b1));
            asm("fma.rn.f32x2 %0, %1, %2, %0;" : "+l"(acc2[i][2]) : "l"(a), "l"(b2));
            asm("fma.rn.f32x2 %0, %1, %2, %0;" : "+l"(acc2[i][3]) : "l"(a), "l"(b3));
        }
    }
    #pragma unroll
    for (int i = 0; i < 4; i++)
        #pragma unroll
        for (int j = 0; j < 4; j++) {
            float lo, hi;
            asm("mov.b64 {%0, %1}, %2;" : "=f"(lo), "=f"(hi) : "l"(acc2[i][j]));
            acc[i][j] = lo + hi;
        }
}

// ---------------- CSR build ----------------
__global__ __launch_bounds__(256) void hist_kernel(const int* __restrict__ dst) {
    int e = blockIdx.x * 256 + threadIdx.x;
    if (e < EE) atomicAdd(&g_deg[dst[e]], 1);
}

__global__ __launch_bounds__(1024) void scan_kernel() {
    __shared__ int wsum[32];
    __shared__ int carry_s;
    int tid = threadIdx.x, lane = tid & 31, wid = tid >> 5;
    if (tid == 0) carry_s = 0;
    __syncthreads();
    for (int base = 0; base < NN; base += 1024) {
        int v = (base + tid < NN) ? g_deg[base + tid] : 0;
        int inc = v;
        #pragma unroll
        for (int off = 1; off < 32; off <<= 1) {
            int t = __shfl_up_sync(0xffffffffu, inc, off);
            if (lane >= off) inc += t;
        }
        if (lane == 31) wsum[wid] = inc;
        __syncthreads();
        if (wid == 0) {
            int s = wsum[lane];
            #pragma unroll
            for (int off = 1; off < 32; off <<= 1) {
                int t = __shfl_up_sync(0xffffffffu, s, off);
                if (lane >= off) s += t;
            }
            wsum[lane] = s;
        }
        __syncthreads();
        int wpre = wid ? wsum[wid - 1] : 0;
        int excl = carry_s + wpre + inc - v;
        if (base + tid < NN) g_off[base + tid] = excl;
        __syncthreads();
        if (tid == 0) carry_s += wsum[31];
        __syncthreads();
    }
    if (threadIdx.x == 0) g_off[NN] = carry_s;
}

__global__ __launch_bounds__(256) void fill_kernel(const int* __restrict__ src,
                                                   const int* __restrict__ dst) {
    int e = blockIdx.x * 256 + threadIdx.x;
    if (e < EE) {
        int d = dst[e];
        int pos = g_off[d] + atomicAdd(&g_fill[d], 1);
        g_csr_src[pos] = src[e];
        g_csr_dst[pos] = d;
        g_csr_eid[pos] = e;
    }
}

// ---------------- encoder GIN layer ----------------
__global__ __launch_bounds__(256) void ginenc_kernel(
    const float* __restrict__ hin, float* __restrict__ hout,
    const float* __restrict__ eps_ptr, int lidx,
    const float* __restrict__ W1, const float* __restrict__ b1,
    const float* __restrict__ W2, const float* __restrict__ b2,
    float* __restrict__ pool, const int* __restrict__ batch)
{
    __shared__ __align__(16) float As[64 * SPAD];
    __shared__ __align__(16) float Ws0[32 * WSPS];
    __shared__ __align__(16) float Ws1[32 * WSPS];
    __shared__ float bsh[64], bsh2[64];
    int tid = threadIdx.x;
    int r0 = blockIdx.x * 64;
    float epsv = 1.0f + eps_ptr[lidx];
    int part = tid & 15, grp = tid >> 4;

    #pragma unroll
    for (int rr = 0; rr < 4; rr++) {
        int row = rr * 16 + grp;
        int gr = r0 + row;
        float4 a = make_float4(0.f, 0.f, 0.f, 0.f);
        if (gr < NN) {
            float4 h = ((const float4*)(hin + (size_t)gr * HH))[part];
            a.x = epsv * h.x; a.y = epsv * h.y; a.z = epsv * h.z; a.w = epsv * h.w;
            int beg = g_off[gr], end = g_off[gr + 1];
            int p = beg;
            for (; p + 1 < end; p += 2) {
                int s0 = g_csr_src[p], s1 = g_csr_src[p + 1];
                float4 v0 = ((const float4*)(hin + (size_t)s0 * HH))[part];
                float4 v1 = ((const float4*)(hin + (size_t)s1 * HH))[part];
                a.x += v0.x + v1.x; a.y += v0.y + v1.y;
                a.z += v0.z + v1.z; a.w += v0.w + v1.w;
            }
            if (p < end) {
                int s0 = g_csr_src[p];
                float4 v0 = ((const float4*)(hin + (size_t)s0 * HH))[part];
                a.x += v0.x; a.y += v0.y; a.z += v0.z; a.w += v0.w;
            }
        }
        *((float4*)&As[row * SPAD + part * 4]) = a;
    }

    loadWp(W1, Ws0, tid);
    loadWp(W2, Ws1, tid);
    if (tid < 64) { bsh[tid] = b1[tid]; bsh2[tid] = b2[tid]; }
    __syncthreads();

    int tx = tid & 15, ty = tid >> 4;
    float acc[4][4];
    gemm64p(As, Ws0, acc, tx, ty);
    __syncthreads();
    #pragma unroll
    for (int i = 0; i < 4; i++) {
        float4 h;
        h.x = fmaxf(acc[i][0] + bsh[tx*4+0], 0.f);
        h.y = fmaxf(acc[i][1] + bsh[tx*4+1], 0.f);
        h.z = fmaxf(acc[i][2] + bsh[tx*4+2], 0.f);
        h.w = fmaxf(acc[i][3] + bsh[tx*4+3], 0.f);
        *((float4*)&As[(ty * 4 + i) * SPAD + tx * 4]) = h;
    }
    __syncthreads();
    gemm64p(As, Ws1, acc, tx, ty);
    #pragma unroll
    for (int i = 0; i < 4; i++) {
        int go = r0 + ty * 4 + i;
        if (go < NN) {
            float4 o;
            o.x = fmaxf(acc[i][0] + bsh2[tx*4+0], 0.f);
            o.y = fmaxf(acc[i][1] + bsh2[tx*4+1], 0.f);
            o.z = fmaxf(acc[i][2] + bsh2[tx*4+2], 0.f);
            o.w = fmaxf(acc[i][3] + bsh2[tx*4+3], 0.f);
            *((float4*)(hout + (size_t)go * HH + tx * 4)) = o;
            if (pool) {
                int b = batch[go];
                red_add_f4((float4*)(pool + (size_t)b * HH + tx * 4), o);
            }
        }
    }
}

// ---------------- classifier GIN layer, all K experts, interleaved [n][k][64] ----------
__global__ __launch_bounds__(256) void gincl_kernel(
    const float* __restrict__ hin, float* __restrict__ hout,
    const float* __restrict__ eps_ptr, int lidx,
    const float* __restrict__ W1, const float* __restrict__ b1,
    const float* __restrict__ W2, const float* __restrict__ b2,
    float* __restrict__ pool, const int* __restrict__ batch)
{
    __shared__ __align__(16) float As[64 * SPAD];
    __shared__ __align__(16) float Ws0[32 * WSPS];
    __shared__ __align__(16) float Ws1[32 * WSPS];
    __shared__ float bsh[64], bsh2[64];
    int tid = threadIdx.x;
    int n0 = blockIdx.x * 16;
    float epsv = 1.0f + eps_ptr[lidx];
    int part = tid & 15, grp = tid >> 4;

    {
        int gr = n0 + grp;
        const float4* hbase = (const float4*)(hin + (size_t)gr * KK * HH);
        float4 a[4];
        #pragma unroll
        for (int k = 0; k < 4; k++) {
            float4 h = hbase[k * 16 + part];
            a[k].x = epsv * h.x; a[k].y = epsv * h.y;
            a[k].z = epsv * h.z; a[k].w = epsv * h.w;
        }
        int beg = g_off[gr], end = g_off[gr + 1];
        int p = beg;
        int s_next = (p < end) ? g_csr_src[p] : 0;
        for (; p < end; p++) {
            int s = s_next;
            if (p + 1 < end) s_next = g_csr_src[p + 1];
            float4 w4 = *((const float4*)(g_ewc + (size_t)p * 4));
            const float4* vb = (const float4*)(hin + (size_t)s * KK * HH);
            float4 v0 = vb[0 * 16 + part];
            float4 v1 = vb[1 * 16 + part];
            float4 v2 = vb[2 * 16 + part];
            float4 v3 = vb[3 * 16 + part];
            a[0].x = fmaf(w4.x, v0.x, a[0].x); a[0].y = fmaf(w4.x, v0.y, a[0].y);
            a[0].z = fmaf(w4.x, v0.z, a[0].z); a[0].w = fmaf(w4.x, v0.w, a[0].w);
            a[1].x = fmaf(w4.y, v1.x, a[1].x); a[1].y = fmaf(w4.y, v1.y, a[1].y);
            a[1].z = fmaf(w4.y, v1.z, a[1].z); a[1].w = fmaf(w4.y, v1.w, a[1].w);
            a[2].x = fmaf(w4.z, v2.x, a[2].x); a[2].y = fmaf(w4.z, v2.y, a[2].y);
            a[2].z = fmaf(w4.z, v2.z, a[2].z); a[2].w = fmaf(w4.z, v2.w, a[2].w);
            a[3].x = fmaf(w4.w, v3.x, a[3].x); a[3].y = fmaf(w4.w, v3.y, a[3].y);
            a[3].z = fmaf(w4.w, v3.z, a[3].z); a[3].w = fmaf(w4.w, v3.w, a[3].w);
        }
        #pragma unroll
        for (int k = 0; k < 4; k++)
            *((float4*)&As[(grp * 4 + k) * SPAD + part * 4]) = a[k];
    }

    loadWp(W1, Ws0, tid);
    loadWp(W2, Ws1, tid);
    if (tid < 64) { bsh[tid] = b1[tid]; bsh2[tid] = b2[tid]; }
    __syncthreads();

    int tx = tid & 15, ty = tid >> 4;
    float acc[4][4];
    gemm64p(As, Ws0, acc, tx, ty);
    __syncthreads();
    #pragma unroll
    for (int i = 0; i < 4; i++) {
        float4 h;
        h.x = fmaxf(acc[i][0] + bsh[tx*4+0], 0.f);
        h.y = fmaxf(acc[i][1] + bsh[tx*4+1], 0.f);
        h.z = fmaxf(acc[i][2] + bsh[tx*4+2], 0.f);
        h.w = fmaxf(acc[i][3] + bsh[tx*4+3], 0.f);
        *((float4*)&As[(ty * 4 + i) * SPAD + tx * 4]) = h;
    }
    __syncthreads();
    gemm64p(As, Ws1, acc, tx, ty);
    #pragma unroll
    for (int i = 0; i < 4; i++) {
        int row = ty * 4 + i;
        int gn = n0 + (row >> 2);
        int ke = row & 3;
        float4 o;
        o.x = fmaxf(acc[i][0] + bsh2[tx*4+0], 0.f);
        o.y = fmaxf(acc[i][1] + bsh2[tx*4+1], 0.f);
        o.z = fmaxf(acc[i][2] + bsh2[tx*4+2], 0.f);
        o.w = fmaxf(acc[i][3] + bsh2[tx*4+3], 0.f);
        *((float4*)(hout + ((size_t)gn * KK + ke) * HH + tx * 4)) = o;
        if (pool) {
            int b = batch[gn];
            red_add_f4((float4*)(pool + ((size_t)ke * NB_BATCH + b) * HH + tx * 4), o);
        }
    }
}

// ---------------- fused mask kernel: nm + AB precompute + fm + masked_x ----------------
__global__ __launch_bounds__(256) void mask_kernel(
    const float* __restrict__ Z, const float* __restrict__ x,
    const float* __restrict__ nmW1, const float* __restrict__ nmb1,
    const float* __restrict__ nmW2, const float* __restrict__ nmb2,
    const float* __restrict__ emW1,
    const float* __restrict__ fmW1, const float* __restrict__ fmb1,
    const float* __restrict__ fmW2, const float* __restrict__ fmb2,
    float* __restrict__ out_nm, float* __restrict__ out_fm)
{
    __shared__ __align__(16) float As[64 * SPAD];
    __shared__ __align__(16) float Ws0[32 * WSPS];
    __shared__ __align__(16) float Ws1[32 * WSPS];
    __shared__ float bsh[64], bsh2[64], w2s[64], nmv[64];
    int tid = threadIdx.x, r0 = blockIdx.x * 64;
    int k = blockIdx.y;
    const float* nmW1k = nmW1 + (size_t)k * 4096;
    const float* nmb1k = nmb1 + (size_t)k * 64;
    const float* nmW2k = nmW2 + (size_t)k * 64;
    const float* emW1k = emW1 + (size_t)k * 8192;
    const float* fmW1k = fmW1 + (size_t)k * 4096;
    const float* fmb1k = fmb1 + (size_t)k * 64;
    const float* fmW2k = fmW2 + (size_t)k * 4096;
    const float* fmb2k = fmb2 + (size_t)k * 64;
    float* ABk = g_AB + (size_t)k * NN * 128;

    {
        int row = tid >> 2, p0 = (tid & 3) * 4, gr = r0 + row;
        #pragma unroll
        for (int q = 0; q < 4; q++) {
            float4 v = make_float4(0.f, 0.f, 0.f, 0.f);
            if (gr < NN) v = ((const float4*)(Z + (size_t)gr * HH))[p0 + q];
            *((float4*)&As[row * SPAD + (p0 + q) * 4]) = v;
        }
    }
    int tx = tid & 15, ty = tid >> 4;
    float acc[4][4];

    // ---- node mask (Ws0) ; preload em half0 (Ws1) ----
    loadWp(nmW1k, Ws0, tid);
    loadWp(emW1k, Ws1, tid);
    if (tid < 64) { bsh[tid] = nmb1k[tid]; w2s[tid] = nmW2k[tid]; }
    __syncthreads();
    gemm64p(As, Ws0, acc, tx, ty);
    float b2v = nmb2[k];
    #pragma unroll
    for (int i = 0; i < 4; i++) {
        float p = 0.f;
        #pragma unroll
        for (int j = 0; j < 4; j++)
            p += fmaxf(acc[i][j] + bsh[tx*4+j], 0.f) * w2s[tx*4+j];
        #pragma unroll
        for (int off = 8; off > 0; off >>= 1)
            p += __shfl_down_sync(0xffffffffu, p, off, 16);
        if (tx == 0) {
            float sg = sigmoidf_(p + b2v);
            nmv[ty * 4 + i] = sg;
            int gr = r0 + ty * 4 + i;
            if (gr < NN) out_nm[(size_t)gr * KK + k] = sg;
        }
    }
    __syncthreads();

    // ---- AB half0 (Ws1) ; preload em half1 (Ws0) ----
    loadWp(emW1k + 4096, Ws0, tid);
    gemm64p(As, Ws1, acc, tx, ty);
    #pragma unroll
    for (int i = 0; i < 4; i++) {
        int gr = r0 + ty * 4 + i;
        if (gr < NN) {
            float4 o = make_float4(acc[i][0], acc[i][1], acc[i][2], acc[i][3]);
            *((float4*)(ABk + (size_t)gr * 128 + tx * 4)) = o;
        }
    }
    __syncthreads();

    // ---- AB half1 (Ws0) ; preload fm W1 (Ws1) ----
    loadWp(fmW1k, Ws1, tid);
    gemm64p(As, Ws0, acc, tx, ty);
    #pragma unroll
    for (int i = 0; i < 4; i++) {
        int gr = r0 + ty * 4 + i;
        if (gr < NN) {
            float4 o = make_float4(acc[i][0], acc[i][1], acc[i][2], acc[i][3]);
            *((float4*)(ABk + (size_t)gr * 128 + 64 + tx * 4)) = o;
        }
    }
    __syncthreads();

    // ---- fm layer1 (Ws1) ; preload fm W2 (Ws0) ----
    loadWp(fmW2k, Ws0, tid);
    if (tid < 64) { bsh[tid] = fmb1k[tid]; bsh2[tid] = fmb2k[tid]; }
    __syncthreads();
    gemm64p(As, Ws1, acc, tx, ty);
    __syncthreads();
    #pragma unroll
    for (int i = 0; i < 4; i++) {
        float4 h;
        h.x = fmaxf(acc[i][0] + bsh[tx*4+0], 0.f);
        h.y = fmaxf(acc[i][1] + bsh[tx*4+1], 0.f);
        h.z = fmaxf(acc[i][2] + bsh[tx*4+2], 0.f);
        h.w = fmaxf(acc[i][3] + bsh[tx*4+3], 0.f);
        *((float4*)&As[(ty * 4 + i) * SPAD + tx * 4]) = h;
    }
    __syncthreads();
    gemm64p(As, Ws0, acc, tx, ty);
    #pragma unroll
    for (int i = 0; i < 4; i++) {
        int gr = r0 + ty * 4 + i;
        if (gr < NN) {
            float nmu = nmv[ty * 4 + i];
            float4 xr = *((const float4*)(x + (size_t)gr * FF + tx * 4));
            float4 sg;
            sg.x = sigmoidf_(acc[i][0] + bsh2[tx*4+0]);
            sg.y = sigmoidf_(acc[i][1] + bsh2[tx*4+1]);
            sg.z = sigmoidf_(acc[i][2] + bsh2[tx*4+2]);
            sg.w = sigmoidf_(acc[i][3] + bsh2[tx*4+3]);
            *((float4*)(out_fm + ((size_t)gr * KK + k) * FF + tx * 4)) = sg;
            float4 m = make_float4(xr.x * nmu * sg.x, xr.y * nmu * sg.y,
                                   xr.z * nmu * sg.z, xr.w * nmu * sg.w);
            *((float4*)(g_h0 + ((size_t)gr * KK + k) * HH + tx * 4)) = m;
        }
    }
}

// ---------------- edge mask: 16 lanes/edge, iterating CSR positions ----------
__global__ __launch_bounds__(256) void edge_mask_kernel(
    const float* __restrict__ emb1, const float* __restrict__ emW2,
    const float* __restrict__ emb2, float* __restrict__ out_em)
{
    __shared__ __align__(16) float b1s[64];
    __shared__ __align__(16) float w2s[64];
    int tid = threadIdx.x;
    int k = blockIdx.y;
    if (tid < 64) { b1s[tid] = emb1[k * 64 + tid]; w2s[tid] = emW2[k * 64 + tid]; }
    __syncthreads();
    const float* ABk = g_AB + (size_t)k * NN * 128;
    int idx = blockIdx.x * 256 + tid;
    int p = idx >> 4, lane = idx & 15;
    int s = g_csr_src[p], d = g_csr_dst[p];
    float4 a  = *((const float4*)(ABk + (size_t)s * 128) + lane);
    float4 bb = *((const float4*)(ABk + (size_t)d * 128 + 64) + lane);
    float4 bi = ((const float4*)b1s)[lane];
    float4 w  = ((const float4*)w2s)[lane];
    float pp = fmaxf(a.x + bb.x + bi.x, 0.f) * w.x
             + fmaxf(a.y + bb.y + bi.y, 0.f) * w.y
             + fmaxf(a.z + bb.z + bi.z, 0.f) * w.z
             + fmaxf(a.w + bb.w + bi.w, 0.f) * w.w;
    #pragma unroll
    for (int off = 8; off > 0; off >>= 1)
        pp += __shfl_down_sync(0xffffffffu, pp, off, 16);
    if (lane == 0) {
        float sg = sigmoidf_(pp + emb2[k]);
        g_ewc[(size_t)p * KK + k] = sg;
        out_em[(size_t)g_csr_eid[p] * KK + k] = sg;
    }
}

// ---------------- counts ----------------
__global__ __launch_bounds__(256) void cnt_kernel(const int* __restrict__ batch) {
    int idx = blockIdx.x * 256 + threadIdx.x;
    if (idx < NN) atomicAdd(&g_cnt[batch[idx]], 1);
}

// ---------------- finalize ----------------
__global__ __launch_bounds__(64) void finalize_kernel(
    const float* __restrict__ clfW, const float* __restrict__ clfb,
    float* __restrict__ out_logits, float* __restrict__ out_hstab,
    float* __restrict__ out_horig)
{
    int b = blockIdx.x, t = threadIdx.x;
    __shared__ float hs[64];
    float inv = 1.0f / fmaxf((float)g_cnt[b], 1.0f);
    out_horig[b * HH + t] = g_poolZ[b * HH + t] * inv;
    for (int k = 0; k < KK; k++) {
        float v = g_poolS[((size_t)k * NB_BATCH + b) * HH + t] * inv;
        out_hstab[((size_t)b * KK + k) * HH + t] = v;
        hs[t] = v;
        __syncthreads();
        if (t < CC) {
            float sacc = clfb[k * CC + t];
            #pragma unroll 8
            for (int h2 = 0; h2 < HH; h2++)
                sacc += hs[h2] * clfW[((size_t)k * HH + h2) * CC + t];
            out_logits[((size_t)b * KK + k) * CC + t] = sacc;
        }
        __syncthreads();
    }
}

// ---------------- host launch ----------------
extern "C" void kernel_launch(void* const* d_in, const int* in_sizes, int n_in,
                              void* d_out, int out_size)
{
    const float* x     = (const float*)d_in[0];
    const int*   ei    = (const int*)d_in[1];
    const int*   batch = (const int*)d_in[2];
    const float* ceW1  = (const float*)d_in[3];
    const float* ceb1  = (const float*)d_in[4];
    const float* ceW2  = (const float*)d_in[5];
    const float* ceb2  = (const float*)d_in[6];
    const float* ceeps = (const float*)d_in[7];
    const float* clW1  = (const float*)d_in[8];
    const float* clb1  = (const float*)d_in[9];
    const float* clW2  = (const float*)d_in[10];
    const float* clb2  = (const float*)d_in[11];
    const float* cleps = (const float*)d_in[12];
    const float* nmW1  = (const float*)d_in[13];
    const float* nmb1  = (const float*)d_in[14];
    const float* nmW2  = (const float*)d_in[15];
    const float* nmb2  = (const float*)d_in[16];
    const float* emW1  = (const float*)d_in[17];
    const float* emb1  = (const float*)d_in[18];
    const float* emW2  = (const float*)d_in[19];
    const float* emb2  = (const float*)d_in[20];
    const float* fmW1  = (const float*)d_in[21];
    const float* fmb1  = (const float*)d_in[22];
    const float* fmW2  = (const float*)d_in[23];
    const float* fmb2  = (const float*)d_in[24];
    const float* clfW  = (const float*)d_in[25];
    const float* clfb  = (const float*)d_in[26];

    const int* src = ei;
    const int* dst = ei + EE;

    float* Z_p;     cudaGetSymbolAddress((void**)&Z_p, g_Z);
    float* h0_p;    cudaGetSymbolAddress((void**)&h0_p, g_h0);
    float* h1_p;    cudaGetSymbolAddress((void**)&h1_p, g_h1);
    float* poolZ_p; cudaGetSymbolAddress((void**)&poolZ_p, g_poolZ);
    float* poolS_p; cudaGetSymbolAddress((void**)&poolS_p, g_poolS);
    int*   cnt_p;   cudaGetSymbolAddress((void**)&cnt_p, g_cnt);
    int*   deg_p;   cudaGetSymbolAddress((void**)&deg_p, g_deg);
    int*   fill_p;  cudaGetSymbolAddress((void**)&fill_p, g_fill);

    float* out        = (float*)d_out;
    float* out_logits = out;
    float* out_hstab  = out_logits + NB_BATCH * KK * CC;
    float* out_horig  = out_hstab + NB_BATCH * KK * HH;
    float* out_nm     = out_horig + NB_BATCH * HH;
    float* out_em     = out_nm + (size_t)NN * KK;
    float* out_fm     = out_em + (size_t)EE * KK;

    const int GB = (NN + 63) / 64;          // 782
    const int GC = NN / 16;                 // 3125
    const int EG = (EE + 255) / 256;
    const int EDGE_GRID = (EE * 16) / 256;  // 50000

    // ---- CSR build + pool init ----
    cudaMemsetAsync(deg_p, 0, NN * sizeof(int));
    cudaMemsetAsync(fill_p, 0, NN * sizeof(int));
    cudaMemsetAsync(cnt_p, 0, NB_BATCH * sizeof(int));
    cudaMemsetAsync(poolZ_p, 0, (size_t)NB_BATCH * HH * sizeof(float));
    cudaMemsetAsync(poolS_p, 0, (size_t)KK * NB_BATCH * HH * sizeof(float));
    hist_kernel<<<EG, 256>>>(dst);
    cnt_kernel<<<(NN + 255) / 256, 256>>>(batch);
    scan_kernel<<<1, 1024>>>();
    fill_kernel<<<EG, 256>>>(src, dst);

    // ---- causal encoder GIN (3 layers); layer 3 fuses Z pooling ----
    ginenc_kernel<<<GB, 256>>>(x, h1_p, ceeps, 0, ceW1, ceb1, ceW2, ceb2, nullptr, nullptr);
    ginenc_kernel<<<GB, 256>>>(h1_p, h0_p, ceeps, 1, ceW1 + 4096, ceb1 + 64,
                               ceW2 + 4096, ceb2 + 64, nullptr, nullptr);
    ginenc_kernel<<<GB, 256>>>(h0_p, Z_p, ceeps, 2, ceW1 + 8192, ceb1 + 128,
                               ceW2 + 8192, ceb2 + 128, poolZ_p, batch);

    // ---- masks (writes interleaved g_h0) ----
    mask_kernel<<<dim3(GB, KK), 256>>>(Z_p, x, nmW1, nmb1, nmW2, nmb2,
                                       emW1, fmW1, fmb1, fmW2, fmb2,
                                       out_nm, out_fm);
    edge_mask_kernel<<<dim3(EDGE_GRID, KK), 256>>>(emb1, emW2, emb2, out_em);

    // ---- classifier GIN (3 layers, all K); layer 3 fuses pooling ----
    gincl_kernel<<<GC, 256>>>(h0_p, h1_p, cleps, 0, clW1, clb1, clW2, clb2,
                              nullptr, nullptr);
    gincl_kernel<<<GC, 256>>>(h1_p, h0_p, cleps, 1, clW1 + 4096, clb1 + 64,
                              clW2 + 4096, clb2 + 64, nullptr, nullptr);
    gincl_kernel<<<GC, 256>>>(h0_p, h1_p, cleps, 2, clW1 + 8192, clb1 + 128,
                              clW2 + 8192, clb2 + 128, poolS_p, batch);

    // ---- finalize ----
    finalize_kernel<<<NB_BATCH, 64>>>(clfW, clfb, out_logits, out_hstab, out_horig);
}

// round 9
// speedup vs baseline: 1.2889x; 1.2889x over previous
#include <cuda_runtime.h>
#include <math.h>

#define NN 50000
#define EE 800000
#define HH 64
#define FF 64
#define CC 10
#define KK 4
#define LL 3
#define NB_BATCH 256
#define SPAD 68

// ---------------- device scratch ----------------
__device__ float g_Z[NN * HH];
__device__ float g_h0[(size_t)NN * KK * HH];   // interleaved [n][k][64]
__device__ float g_h1[(size_t)NN * KK * HH];   // interleaved [n][k][64]
__device__ float g_AB[(size_t)KK * NN * 128];
__device__ float g_ewc[(size_t)EE * KK];       // CSR-edge-major weights [p][k]
__device__ int   g_deg[NN];
__device__ int   g_off[NN + 1];
__device__ int   g_fill[NN];
__device__ int   g_csr_src[EE];
__device__ int   g_csr_dst[EE];
__device__ int   g_csr_eid[EE];
__device__ float g_poolZ[NB_BATCH * HH];
__device__ float g_poolS[KK * NB_BATCH * HH];
__device__ int   g_cnt[NB_BATCH];

__device__ __forceinline__ void red_add_f4(float4* p, float4 v) {
    asm volatile("red.global.add.v4.f32 [%0], {%1,%2,%3,%4};"
                 :: "l"(p), "f"(v.x), "f"(v.y), "f"(v.z), "f"(v.w) : "memory");
}
__device__ __forceinline__ float sigmoidf_(float v) { return 1.0f / (1.0f + expf(-v)); }

__device__ __forceinline__ void loadW(const float* __restrict__ W, float* Ws, int tid) {
    for (int i = tid; i < 1024; i += 256) {
        float4 w = ((const float4*)W)[i];
        *((float4*)&Ws[(i >> 4) * SPAD + (i & 15) * 4]) = w;
    }
}

// 64x64x64 GEMM with packed f32x2 FMA (FFMA2): As row-major [row][k], Ws [k][col].
__device__ __forceinline__ void gemm64x2(const float* As, const float* Ws,
                                         unsigned long long acc2[4][2], int tx, int ty) {
    #pragma unroll
    for (int i = 0; i < 4; i++)
        #pragma unroll
        for (int j = 0; j < 2; j++) acc2[i][j] = 0ULL;
    #pragma unroll
    for (int kk = 0; kk < 64; kk += 4) {
        unsigned long long bp[4][2];
        #pragma unroll
        for (int s = 0; s < 4; s++) {
            ulonglong2 b2 = *((const ulonglong2*)&Ws[(kk + s) * SPAD + tx * 4]);
            bp[s][0] = b2.x; bp[s][1] = b2.y;
        }
        #pragma unroll
        for (int i = 0; i < 4; i++) {
            float4 a4 = *((const float4*)&As[(ty * 4 + i) * SPAD + kk]);
            float av[4] = {a4.x, a4.y, a4.z, a4.w};
            #pragma unroll
            for (int s = 0; s < 4; s++) {
                unsigned long long ad;
                asm("mov.b64 %0, {%1, %1};" : "=l"(ad) : "f"(av[s]));
                asm("fma.rn.f32x2 %0, %1, %2, %0;"
                    : "+l"(acc2[i][0]) : "l"(ad), "l"(bp[s][0]));
                asm("fma.rn.f32x2 %0, %1, %2, %0;"
                    : "+l"(acc2[i][1]) : "l"(ad), "l"(bp[s][1]));
            }
        }
    }
}

__device__ __forceinline__ void unpack_acc(const unsigned long long acc2[4][2],
                                           float acc[4][4]) {
    #pragma unroll
    for (int i = 0; i < 4; i++)
        #pragma unroll
        for (int j = 0; j < 2; j++) {
            float lo, hi;
            asm("mov.b64 {%0, %1}, %2;" : "=f"(lo), "=f"(hi) : "l"(acc2[i][j]));
            acc[i][2 * j] = lo; acc[i][2 * j + 1] = hi;
        }
}

__device__ __forceinline__ void gemm64(const float* As, const float* Ws,
                                       float acc[4][4], int tx, int ty) {
    unsigned long long a2[4][2];
    gemm64x2(As, Ws, a2, tx, ty);
    unpack_acc(a2, acc);
}

// ---------------- init: zero all accumulators in one launch ----------------
__global__ __launch_bounds__(256) void init_kernel() {
    int i = blockIdx.x * 256 + threadIdx.x;
    if (i < NN) { g_deg[i] = 0; g_fill[i] = 0; }
    if (i < NB_BATCH) g_cnt[i] = 0;
    if (i < NB_BATCH * HH) g_poolZ[i] = 0.f;
    if (i < KK * NB_BATCH * HH) g_poolS[i] = 0.f;
}

// ---------------- CSR build: histogram + batch counts in one kernel ----------------
__global__ __launch_bounds__(256) void histcnt_kernel(const int* __restrict__ dst,
                                                      const int* __restrict__ batch) {
    int e = blockIdx.x * 256 + threadIdx.x;
    if (e < EE) atomicAdd(&g_deg[dst[e]], 1);
    if (e < NN) atomicAdd(&g_cnt[batch[e]], 1);
}

__global__ __launch_bounds__(1024) void scan_kernel() {
    __shared__ int wsum[32];
    __shared__ int carry_s;
    int tid = threadIdx.x, lane = tid & 31, wid = tid >> 5;
    if (tid == 0) carry_s = 0;
    __syncthreads();
    for (int base = 0; base < NN; base += 1024) {
        int v = (base + tid < NN) ? g_deg[base + tid] : 0;
        int inc = v;
        #pragma unroll
        for (int off = 1; off < 32; off <<= 1) {
            int t = __shfl_up_sync(0xffffffffu, inc, off);
            if (lane >= off) inc += t;
        }
        if (lane == 31) wsum[wid] = inc;
        __syncthreads();
        if (wid == 0) {
            int s = wsum[lane];
            #pragma unroll
            for (int off = 1; off < 32; off <<= 1) {
                int t = __shfl_up_sync(0xffffffffu, s, off);
                if (lane >= off) s += t;
            }
            wsum[lane] = s;
        }
        __syncthreads();
        int wpre = wid ? wsum[wid - 1] : 0;
        int excl = carry_s + wpre + inc - v;
        if (base + tid < NN) g_off[base + tid] = excl;
        __syncthreads();
        if (tid == 0) carry_s += wsum[31];
        __syncthreads();
    }
    if (threadIdx.x == 0) g_off[NN] = carry_s;
}

__global__ __launch_bounds__(256) void fill_kernel(const int* __restrict__ src,
                                                   const int* __restrict__ dst) {
    int e = blockIdx.x * 256 + threadIdx.x;
    if (e < EE) {
        int d = dst[e];
        int pos = g_off[d] + atomicAdd(&g_fill[d], 1);
        g_csr_src[pos] = src[e];
        g_csr_dst[pos] = d;
        g_csr_eid[pos] = e;
    }
}

// ---------------- encoder GIN layer ----------------
__global__ __launch_bounds__(256) void ginenc_kernel(
    const float* __restrict__ hin, float* __restrict__ hout,
    const float* __restrict__ eps_ptr, int lidx,
    const float* __restrict__ W1, const float* __restrict__ b1,
    const float* __restrict__ W2, const float* __restrict__ b2,
    float* __restrict__ pool, const int* __restrict__ batch)
{
    __shared__ __align__(16) float As[64 * SPAD];
    __shared__ __align__(16) float Ws[64 * SPAD];
    __shared__ float bsh[64], bsh2[64];
    int tid = threadIdx.x;
    int r0 = blockIdx.x * 64;
    float epsv = 1.0f + eps_ptr[lidx];
    int part = tid & 15, grp = tid >> 4;

    #pragma unroll
    for (int rr = 0; rr < 4; rr++) {
        int row = rr * 16 + grp;
        int gr = r0 + row;
        float4 a = make_float4(0.f, 0.f, 0.f, 0.f);
        if (gr < NN) {
            float4 h = ((const float4*)(hin + (size_t)gr * HH))[part];
            a.x = epsv * h.x; a.y = epsv * h.y; a.z = epsv * h.z; a.w = epsv * h.w;
            int beg = g_off[gr], end = g_off[gr + 1];
            int p = beg;
            for (; p + 1 < end; p += 2) {
                int s0 = g_csr_src[p], s1 = g_csr_src[p + 1];
                float4 v0 = ((const float4*)(hin + (size_t)s0 * HH))[part];
                float4 v1 = ((const float4*)(hin + (size_t)s1 * HH))[part];
                a.x += v0.x + v1.x; a.y += v0.y + v1.y;
                a.z += v0.z + v1.z; a.w += v0.w + v1.w;
            }
            if (p < end) {
                int s0 = g_csr_src[p];
                float4 v0 = ((const float4*)(hin + (size_t)s0 * HH))[part];
                a.x += v0.x; a.y += v0.y; a.z += v0.z; a.w += v0.w;
            }
        }
        *((float4*)&As[row * SPAD + part * 4]) = a;
    }

    loadW(W1, Ws, tid);
    if (tid < 64) { bsh[tid] = b1[tid]; bsh2[tid] = b2[tid]; }
    __syncthreads();

    int tx = tid & 15, ty = tid >> 4;
    float acc[4][4];
    gemm64(As, Ws, acc, tx, ty);
    __syncthreads();
    #pragma unroll
    for (int i = 0; i < 4; i++) {
        float4 h;
        h.x = fmaxf(acc[i][0] + bsh[tx*4+0], 0.f);
        h.y = fmaxf(acc[i][1] + bsh[tx*4+1], 0.f);
        h.z = fmaxf(acc[i][2] + bsh[tx*4+2], 0.f);
        h.w = fmaxf(acc[i][3] + bsh[tx*4+3], 0.f);
        *((float4*)&As[(ty * 4 + i) * SPAD + tx * 4]) = h;
    }
    loadW(W2, Ws, tid);
    __syncthreads();
    gemm64(As, Ws, acc, tx, ty);
    #pragma unroll
    for (int i = 0; i < 4; i++) {
        int go = r0 + ty * 4 + i;
        if (go < NN) {
            float4 o;
            o.x = fmaxf(acc[i][0] + bsh2[tx*4+0], 0.f);
            o.y = fmaxf(acc[i][1] + bsh2[tx*4+1], 0.f);
            o.z = fmaxf(acc[i][2] + bsh2[tx*4+2], 0.f);
            o.w = fmaxf(acc[i][3] + bsh2[tx*4+3], 0.f);
            *((float4*)(hout + (size_t)go * HH + tx * 4)) = o;
            if (pool) {
                int b = batch[go];
                red_add_f4((float4*)(pool + (size_t)b * HH + tx * 4), o);
            }
        }
    }
}

// ---------------- classifier GIN layer, all K experts, interleaved [n][k][64] ----------
__global__ __launch_bounds__(256) void gincl_kernel(
    const float* __restrict__ hin, float* __restrict__ hout,
    const float* __restrict__ eps_ptr, int lidx,
    const float* __restrict__ W1, const float* __restrict__ b1,
    const float* __restrict__ W2, const float* __restrict__ b2,
    float* __restrict__ pool, const int* __restrict__ batch)
{
    __shared__ __align__(16) float As[64 * SPAD];
    __shared__ __align__(16) float Ws[64 * SPAD];
    __shared__ float bsh[64], bsh2[64];
    int tid = threadIdx.x;
    int n0 = blockIdx.x * 16;
    float epsv = 1.0f + eps_ptr[lidx];
    int part = tid & 15, grp = tid >> 4;

    {
        int gr = n0 + grp;
        const float4* hbase = (const float4*)(hin + (size_t)gr * KK * HH);
        float4 a[4];
        #pragma unroll
        for (int k = 0; k < 4; k++) {
            float4 h = hbase[k * 16 + part];
            a[k].x = epsv * h.x; a[k].y = epsv * h.y;
            a[k].z = epsv * h.z; a[k].w = epsv * h.w;
        }
        int beg = g_off[gr], end = g_off[gr + 1];
        int p = beg;
        int s_next = (p < end) ? g_csr_src[p] : 0;
        for (; p < end; p++) {
            int s = s_next;
            if (p + 1 < end) s_next = g_csr_src[p + 1];
            float4 w4 = *((const float4*)(g_ewc + (size_t)p * 4));
            const float4* vb = (const float4*)(hin + (size_t)s * KK * HH);
            float4 v0 = vb[0 * 16 + part];
            float4 v1 = vb[1 * 16 + part];
            float4 v2 = vb[2 * 16 + part];
            float4 v3 = vb[3 * 16 + part];
            a[0].x = fmaf(w4.x, v0.x, a[0].x); a[0].y = fmaf(w4.x, v0.y, a[0].y);
            a[0].z = fmaf(w4.x, v0.z, a[0].z); a[0].w = fmaf(w4.x, v0.w, a[0].w);
            a[1].x = fmaf(w4.y, v1.x, a[1].x); a[1].y = fmaf(w4.y, v1.y, a[1].y);
            a[1].z = fmaf(w4.y, v1.z, a[1].z); a[1].w = fmaf(w4.y, v1.w, a[1].w);
            a[2].x = fmaf(w4.z, v2.x, a[2].x); a[2].y = fmaf(w4.z, v2.y, a[2].y);
            a[2].z = fmaf(w4.z, v2.z, a[2].z); a[2].w = fmaf(w4.z, v2.w, a[2].w);
            a[3].x = fmaf(w4.w, v3.x, a[3].x); a[3].y = fmaf(w4.w, v3.y, a[3].y);
            a[3].z = fmaf(w4.w, v3.z, a[3].z); a[3].w = fmaf(w4.w, v3.w, a[3].w);
        }
        #pragma unroll
        for (int k = 0; k < 4; k++)
            *((float4*)&As[(grp * 4 + k) * SPAD + part * 4]) = a[k];
    }

    loadW(W1, Ws, tid);
    if (tid < 64) { bsh[tid] = b1[tid]; bsh2[tid] = b2[tid]; }
    __syncthreads();

    int tx = tid & 15, ty = tid >> 4;
    float acc[4][4];
    gemm64(As, Ws, acc, tx, ty);
    __syncthreads();
    #pragma unroll
    for (int i = 0; i < 4; i++) {
        float4 h;
        h.x = fmaxf(acc[i][0] + bsh[tx*4+0], 0.f);
        h.y = fmaxf(acc[i][1] + bsh[tx*4+1], 0.f);
        h.z = fmaxf(acc[i][2] + bsh[tx*4+2], 0.f);
        h.w = fmaxf(acc[i][3] + bsh[tx*4+3], 0.f);
        *((float4*)&As[(ty * 4 + i) * SPAD + tx * 4]) = h;
    }
    loadW(W2, Ws, tid);
    __syncthreads();
    gemm64(As, Ws, acc, tx, ty);
    #pragma unroll
    for (int i = 0; i < 4; i++) {
        int row = ty * 4 + i;
        int gn = n0 + (row >> 2);
        int ke = row & 3;
        float4 o;
        o.x = fmaxf(acc[i][0] + bsh2[tx*4+0], 0.f);
        o.y = fmaxf(acc[i][1] + bsh2[tx*4+1], 0.f);
        o.z = fmaxf(acc[i][2] + bsh2[tx*4+2], 0.f);
        o.w = fmaxf(acc[i][3] + bsh2[tx*4+3], 0.f);
        *((float4*)(hout + ((size_t)gn * KK + ke) * HH + tx * 4)) = o;
        if (pool) {
            int b = batch[gn];
            red_add_f4((float4*)(pool + ((size_t)ke * NB_BATCH + b) * HH + tx * 4), o);
        }
    }
}

// ---------------- fused mask kernel: nm + AB precompute + fm + masked_x ----------------
__global__ __launch_bounds__(256) void mask_kernel(
    const float* __restrict__ Z, const float* __restrict__ x,
    const float* __restrict__ nmW1, const float* __restrict__ nmb1,
    const float* __restrict__ nmW2, const float* __restrict__ nmb2,
    const float* __restrict__ emW1,
    const float* __restrict__ fmW1, const float* __restrict__ fmb1,
    const float* __restrict__ fmW2, const float* __restrict__ fmb2,
    float* __restrict__ out_nm, float* __restrict__ out_fm)
{
    __shared__ __align__(16) float As[64 * SPAD];
    __shared__ __align__(16) float Ws[64 * SPAD];
    __shared__ float bsh[64], bsh2[64], w2s[64], nmv[64];
    int tid = threadIdx.x, r0 = blockIdx.x * 64;
    int k = blockIdx.y;
    const float* nmW1k = nmW1 + (size_t)k * 4096;
    const float* nmb1k = nmb1 + (size_t)k * 64;
    const float* nmW2k = nmW2 + (size_t)k * 64;
    const float* emW1k = emW1 + (size_t)k * 8192;
    const float* fmW1k = fmW1 + (size_t)k * 4096;
    const float* fmb1k = fmb1 + (size_t)k * 64;
    const float* fmW2k = fmW2 + (size_t)k * 4096;
    const float* fmb2k = fmb2 + (size_t)k * 64;
    float* ABk = g_AB + (size_t)k * NN * 128;

    {
        int row = tid >> 2, p0 = (tid & 3) * 4, gr = r0 + row;
        #pragma unroll
        for (int q = 0; q < 4; q++) {
            float4 v = make_float4(0.f, 0.f, 0.f, 0.f);
            if (gr < NN) v = ((const float4*)(Z + (size_t)gr * HH))[p0 + q];
            *((float4*)&As[row * SPAD + (p0 + q) * 4]) = v;
        }
    }
    int tx = tid & 15, ty = tid >> 4;
    float acc[4][4];

    // ---- node mask ----
    loadW(nmW1k, Ws, tid);
    if (tid < 64) { bsh[tid] = nmb1k[tid]; w2s[tid] = nmW2k[tid]; }
    __syncthreads();
    gemm64(As, Ws, acc, tx, ty);
    float b2v = nmb2[k];
    #pragma unroll
    for (int i = 0; i < 4; i++) {
        float p = 0.f;
        #pragma unroll
        for (int j = 0; j < 4; j++)
            p += fmaxf(acc[i][j] + bsh[tx*4+j], 0.f) * w2s[tx*4+j];
        #pragma unroll
        for (int off = 8; off > 0; off >>= 1)
            p += __shfl_down_sync(0xffffffffu, p, off, 16);
        if (tx == 0) {
            float sg = sigmoidf_(p + b2v);
            nmv[ty * 4 + i] = sg;
            int gr = r0 + ty * 4 + i;
            if (gr < NN) out_nm[(size_t)gr * KK + k] = sg;
        }
    }

    // ---- AB precompute ----
    #pragma unroll
    for (int half = 0; half < 2; half++) {
        __syncthreads();
        loadW(emW1k + half * 4096, Ws, tid);
        __syncthreads();
        gemm64(As, Ws, acc, tx, ty);
        #pragma unroll
        for (int i = 0; i < 4; i++) {
            int gr = r0 + ty * 4 + i;
            if (gr < NN) {
                float4 o = make_float4(acc[i][0], acc[i][1], acc[i][2], acc[i][3]);
                *((float4*)(ABk + (size_t)gr * 128 + half * 64 + tx * 4)) = o;
            }
        }
    }

    // ---- feature mask + masked_x (interleaved h0 store) ----
    __syncthreads();
    loadW(fmW1k, Ws, tid);
    if (tid < 64) { bsh[tid] = fmb1k[tid]; bsh2[tid] = fmb2k[tid]; }
    __syncthreads();
    gemm64(As, Ws, acc, tx, ty);
    __syncthreads();
    #pragma unroll
    for (int i = 0; i < 4; i++) {
        float4 h;
        h.x = fmaxf(acc[i][0] + bsh[tx*4+0], 0.f);
        h.y = fmaxf(acc[i][1] + bsh[tx*4+1], 0.f);
        h.z = fmaxf(acc[i][2] + bsh[tx*4+2], 0.f);
        h.w = fmaxf(acc[i][3] + bsh[tx*4+3], 0.f);
        *((float4*)&As[(ty * 4 + i) * SPAD + tx * 4]) = h;
    }
    loadW(fmW2k, Ws, tid);
    __syncthreads();
    gemm64(As, Ws, acc, tx, ty);
    #pragma unroll
    for (int i = 0; i < 4; i++) {
        int gr = r0 + ty * 4 + i;
        if (gr < NN) {
            float nmu = nmv[ty * 4 + i];
            float4 xr = *((const float4*)(x + (size_t)gr * FF + tx * 4));
            float4 sg;
            sg.x = sigmoidf_(acc[i][0] + bsh2[tx*4+0]);
            sg.y = sigmoidf_(acc[i][1] + bsh2[tx*4+1]);
            sg.z = sigmoidf_(acc[i][2] + bsh2[tx*4+2]);
            sg.w = sigmoidf_(acc[i][3] + bsh2[tx*4+3]);
            *((float4*)(out_fm + ((size_t)gr * KK + k) * FF + tx * 4)) = sg;
            float4 m = make_float4(xr.x * nmu * sg.x, xr.y * nmu * sg.y,
                                   xr.z * nmu * sg.z, xr.w * nmu * sg.w);
            *((float4*)(g_h0 + ((size_t)gr * KK + k) * HH + tx * 4)) = m;
        }
    }
}

// ---------------- edge mask: 16 lanes/edge, iterating CSR positions ----------
__global__ __launch_bounds__(256) void edge_mask_kernel(
    const float* __restrict__ emb1, const float* __restrict__ emW2,
    const float* __restrict__ emb2, float* __restrict__ out_em)
{
    __shared__ __align__(16) float b1s[64];
    __shared__ __align__(16) float w2s[64];
    int tid = threadIdx.x;
    int k = blockIdx.y;
    if (tid < 64) { b1s[tid] = emb1[k * 64 + tid]; w2s[tid] = emW2[k * 64 + tid]; }
    __syncthreads();
    const float* ABk = g_AB + (size_t)k * NN * 128;
    int idx = blockIdx.x * 256 + tid;
    int p = idx >> 4, lane = idx & 15;
    int s = g_csr_src[p], d = g_csr_dst[p];
    float4 a  = *((const float4*)(ABk + (size_t)s * 128) + lane);
    float4 bb = *((const float4*)(ABk + (size_t)d * 128 + 64) + lane);
    float4 bi = ((const float4*)b1s)[lane];
    float4 w  = ((const float4*)w2s)[lane];
    float pp = fmaxf(a.x + bb.x + bi.x, 0.f) * w.x
             + fmaxf(a.y + bb.y + bi.y, 0.f) * w.y
             + fmaxf(a.z + bb.z + bi.z, 0.f) * w.z
             + fmaxf(a.w + bb.w + bi.w, 0.f) * w.w;
    #pragma unroll
    for (int off = 8; off > 0; off >>= 1)
        pp += __shfl_down_sync(0xffffffffu, pp, off, 16);
    if (lane == 0) {
        float sg = sigmoidf_(pp + emb2[k]);
        g_ewc[(size_t)p * KK + k] = sg;
        out_em[(size_t)g_csr_eid[p] * KK + k] = sg;
    }
}

// ---------------- finalize ----------------
__global__ __launch_bounds__(64) void finalize_kernel(
    const float* __restrict__ clfW, const float* __restrict__ clfb,
    float* __restrict__ out_logits, float* __restrict__ out_hstab,
    float* __restrict__ out_horig)
{
    int b = blockIdx.x, t = threadIdx.x;
    __shared__ float hs[64];
    float inv = 1.0f / fmaxf((float)g_cnt[b], 1.0f);
    out_horig[b * HH + t] = g_poolZ[b * HH + t] * inv;
    for (int k = 0; k < KK; k++) {
        float v = g_poolS[((size_t)k * NB_BATCH + b) * HH + t] * inv;
        out_hstab[((size_t)b * KK + k) * HH + t] = v;
        hs[t] = v;
        __syncthreads();
        if (t < CC) {
            float sacc = clfb[k * CC + t];
            #pragma unroll 8
            for (int h2 = 0; h2 < HH; h2++)
                sacc += hs[h2] * clfW[((size_t)k * HH + h2) * CC + t];
            out_logits[((size_t)b * KK + k) * CC + t] = sacc;
        }
        __syncthreads();
    }
}

// ---------------- host launch ----------------
extern "C" void kernel_launch(void* const* d_in, const int* in_sizes, int n_in,
                              void* d_out, int out_size)
{
    const float* x     = (const float*)d_in[0];
    const int*   ei    = (const int*)d_in[1];
    const int*   batch = (const int*)d_in[2];
    const float* ceW1  = (const float*)d_in[3];
    const float* ceb1  = (const float*)d_in[4];
    const float* ceW2  = (const float*)d_in[5];
    const float* ceb2  = (const float*)d_in[6];
    const float* ceeps = (const float*)d_in[7];
    const float* clW1  = (const float*)d_in[8];
    const float* clb1  = (const float*)d_in[9];
    const float* clW2  = (const float*)d_in[10];
    const float* clb2  = (const float*)d_in[11];
    const float* cleps = (const float*)d_in[12];
    const float* nmW1  = (const float*)d_in[13];
    const float* nmb1  = (const float*)d_in[14];
    const float* nmW2  = (const float*)d_in[15];
    const float* nmb2  = (const float*)d_in[16];
    const float* emW1  = (const float*)d_in[17];
    const float* emb1  = (const float*)d_in[18];
    const float* emW2  = (const float*)d_in[19];
    const float* emb2  = (const float*)d_in[20];
    const float* fmW1  = (const float*)d_in[21];
    const float* fmb1  = (const float*)d_in[22];
    const float* fmW2  = (const float*)d_in[23];
    const float* fmb2  = (const float*)d_in[24];
    const float* clfW  = (const float*)d_in[25];
    const float* clfb  = (const float*)d_in[26];

    const int* src = ei;
    const int* dst = ei + EE;

    float* Z_p;     cudaGetSymbolAddress((void**)&Z_p, g_Z);
    float* h0_p;    cudaGetSymbolAddress((void**)&h0_p, g_h0);
    float* h1_p;    cudaGetSymbolAddress((void**)&h1_p, g_h1);
    float* poolZ_p; cudaGetSymbolAddress((void**)&poolZ_p, g_poolZ);
    float* poolS_p; cudaGetSymbolAddress((void**)&poolS_p, g_poolS);

    float* out        = (float*)d_out;
    float* out_logits = out;
    float* out_hstab  = out_logits + NB_BATCH * KK * CC;
    float* out_horig  = out_hstab + NB_BATCH * KK * HH;
    float* out_nm     = out_horig + NB_BATCH * HH;
    float* out_em     = out_nm + (size_t)NN * KK;
    float* out_fm     = out_em + (size_t)EE * KK;

    const int GB = (NN + 63) / 64;          // 782
    const int GC = NN / 16;                 // 3125
    const int EG = (EE + 255) / 256;        // 3125
    const int EDGE_GRID = (EE * 16) / 256;  // 50000
    const int IG = (KK * NB_BATCH * HH + 255) / 256;  // covers largest init range

    // ---- CSR build + init (single init launch) ----
    init_kernel<<<IG, 256>>>();
    histcnt_kernel<<<EG, 256>>>(dst, batch);
    scan_kernel<<<1, 1024>>>();
    fill_kernel<<<EG, 256>>>(src, dst);

    // ---- causal encoder GIN (3 layers); layer 3 fuses Z pooling ----
    ginenc_kernel<<<GB, 256>>>(x, h1_p, ceeps, 0, ceW1, ceb1, ceW2, ceb2, nullptr, nullptr);
    ginenc_kernel<<<GB, 256>>>(h1_p, h0_p, ceeps, 1, ceW1 + 4096, ceb1 + 64,
                               ceW2 + 4096, ceb2 + 64, nullptr, nullptr);
    ginenc_kernel<<<GB, 256>>>(h0_p, Z_p, ceeps, 2, ceW1 + 8192, ceb1 + 128,
                               ceW2 + 8192, ceb2 + 128, poolZ_p, batch);

    // ---- masks (writes interleaved g_h0) ----
    mask_kernel<<<dim3(GB, KK), 256>>>(Z_p, x, nmW1, nmb1, nmW2, nmb2,
                                       emW1, fmW1, fmb1, fmW2, fmb2,
                                       out_nm, out_fm);
    edge_mask_kernel<<<dim3(EDGE_GRID, KK), 256>>>(emb1, emW2, emb2, out_em);

    // ---- classifier GIN (3 layers, all K); layer 3 fuses pooling ----
    gincl_kernel<<<GC, 256>>>(h0_p, h1_p, cleps, 0, clW1, clb1, clW2, clb2,
                              nullptr, nullptr);
    gincl_kernel<<<GC, 256>>>(h1_p, h0_p, cleps, 1, clW1 + 4096, clb1 + 64,
                              clW2 + 4096, clb2 + 64, nullptr, nullptr);
    gincl_kernel<<<GC, 256>>>(h0_p, h1_p, cleps, 2, clW1 + 8192, clb1 + 128,
                              clW2 + 8192, clb2 + 128, poolS_p, batch);

    // ---- finalize ----
    finalize_kernel<<<NB_BATCH, 64>>>(clfW, clfb, out_logits, out_hstab, out_horig);
}